// round 2
// baseline (speedup 1.0000x reference)
#include <cuda_runtime.h>
#include <cuda_bf16.h>
#include <cstdint>

// Problem constants (fixed shapes per reference)
#define N_NODES 100000
#define N_EDGES 1600000
#define IN_C    128
#define HID_C   128
#define OUT_C   64

// ---------------- device scratch (no allocation allowed) ----------------
__device__ float g_h1[(size_t)N_NODES * HID_C];    // X@W1
__device__ float g_agg1[(size_t)N_NODES * HID_C];  // scatter accum; becomes h (relu'd) in place
__device__ float g_h2[(size_t)N_NODES * OUT_C];    // h@W2
__device__ int   g_deg[N_NODES];
__device__ float g_dinv[N_NODES];

// ---------------- zero kernel (float4 grid-stride) ----------------
__global__ void zero_kernel(float4* __restrict__ p, int n4) {
    int i = blockIdx.x * blockDim.x + threadIdx.x;
    int stride = gridDim.x * blockDim.x;
    float4 z = make_float4(0.f, 0.f, 0.f, 0.f);
    for (; i < n4; i += stride) p[i] = z;
}

// ---------------- degree histogram ----------------
__global__ void hist_kernel(const int* __restrict__ dst, int E) {
    int i = blockIdx.x * blockDim.x + threadIdx.x;
    if (i < E) atomicAdd(&g_deg[dst[i]], 1);
}

__global__ void dinv_kernel(int n) {
    int i = blockIdx.x * blockDim.x + threadIdx.x;
    if (i < n) g_dinv[i] = rsqrtf((float)g_deg[i] + 1.0f);
}

// ---------------- fp32 SIMT GEMM: Y[n, NC] = X[n, 128] @ W[128, NC] ----------------
template <int NC>
__global__ void gemm_kernel(const float* __restrict__ X, const float* __restrict__ W,
                            float* __restrict__ Y, int nrows) {
    constexpr int K = 128;
    constexpr int BM = 64;
    constexpr int TCOLS = NC / 4;        // threads along col dim (32 or 16)
    constexpr int TROWS = 256 / TCOLS;   // 8 or 16
    constexpr int MR = BM / TROWS;       // 8 or 4 rows per thread

    extern __shared__ float smem[];
    float* Ws = smem;            // K * NC
    float* Xs = smem + K * NC;   // BM * K

    int tid = threadIdx.x;

    // load full W into smem
    for (int i = tid; i < K * NC / 4; i += 256)
        ((float4*)Ws)[i] = ((const float4*)W)[i];

    // load X tile (guard tail rows)
    int row0 = blockIdx.x * BM;
    for (int i = tid; i < BM * K / 4; i += 256) {
        int r = i / (K / 4);
        int c = i % (K / 4);
        float4 v = make_float4(0.f, 0.f, 0.f, 0.f);
        if (row0 + r < nrows)
            v = ((const float4*)(X + (size_t)(row0 + r) * K))[c];
        ((float4*)Xs)[i] = v;
    }
    __syncthreads();

    int tc = tid % TCOLS;
    int tr = tid / TCOLS;

    float acc[MR][4];
#pragma unroll
    for (int i = 0; i < MR; i++)
#pragma unroll
        for (int j = 0; j < 4; j++) acc[i][j] = 0.f;

#pragma unroll 4
    for (int k = 0; k < K; k++) {
        float4 b = ((float4*)(Ws + k * NC))[tc];
#pragma unroll
        for (int i = 0; i < MR; i++) {
            float a = Xs[(tr * MR + i) * K + k];
            acc[i][0] += a * b.x;
            acc[i][1] += a * b.y;
            acc[i][2] += a * b.z;
            acc[i][3] += a * b.w;
        }
    }

#pragma unroll
    for (int i = 0; i < MR; i++) {
        int r = row0 + tr * MR + i;
        if (r < nrows) {
            float4 v = make_float4(acc[i][0], acc[i][1], acc[i][2], acc[i][3]);
            ((float4*)(Y + (size_t)r * NC))[tc] = v;
        }
    }
}

// ---------------- edge scatter: agg[dst] += h[src] * dinv[src]*dinv[dst] ----------------
// one warp per edge; C/4 lanes each do one float4 gather + one vector red
template <int C>
__global__ void scatter_kernel(const float* __restrict__ H,
                               const int* __restrict__ src, const int* __restrict__ dst,
                               float* __restrict__ agg, int E) {
    int w = (int)((blockIdx.x * (size_t)blockDim.x + threadIdx.x) >> 5);
    int lane = threadIdx.x & 31;
    if (w >= E) return;
    int s = src[w];
    int d = dst[w];
    float norm = g_dinv[s] * g_dinv[d];
    if (lane < C / 4) {
        float4 v = ((const float4*)(H + (size_t)s * C))[lane];
        float4 m = make_float4(v.x * norm, v.y * norm, v.z * norm, v.w * norm);
        atomicAdd((float4*)(agg + (size_t)d * C) + lane, m);   // red.global.v4.f32 (sm_90+)
    }
}

// ---------------- combine: out = agg + Hself*dinv^2 + bias, optional relu ----------------
template <int C, bool RELU>
__global__ void combine_kernel(const float* __restrict__ agg, const float* __restrict__ Hself,
                               const float* __restrict__ bias, float* __restrict__ out, int n) {
    int i = blockIdx.x * blockDim.x + threadIdx.x;
    int total = n * (C / 4);
    if (i >= total) return;
    int node = i / (C / 4);
    int col4 = i % (C / 4);
    float di = g_dinv[node];
    float d2 = di * di;
    float4 a = ((const float4*)agg)[i];
    float4 h = ((const float4*)Hself)[i];
    float4 b = ((const float4*)bias)[col4];
    float4 r;
    r.x = a.x + h.x * d2 + b.x;
    r.y = a.y + h.y * d2 + b.y;
    r.z = a.z + h.z * d2 + b.z;
    r.w = a.w + h.w * d2 + b.w;
    if (RELU) {
        r.x = fmaxf(r.x, 0.f);
        r.y = fmaxf(r.y, 0.f);
        r.z = fmaxf(r.z, 0.f);
        r.w = fmaxf(r.w, 0.f);
    }
    ((float4*)out)[i] = r;
}

// ---------------- launch ----------------
extern "C" void kernel_launch(void* const* d_in, const int* in_sizes, int n_in,
                              void* d_out, int out_size) {
    const float* x  = (const float*)d_in[0];
    const int*   ei = (const int*)d_in[1];
    const float* W1 = (const float*)d_in[2];
    const float* b1 = (const float*)d_in[3];
    const float* W2 = (const float*)d_in[4];
    const float* b2 = (const float*)d_in[5];
    float* out = (float*)d_out;

    const int N = N_NODES;
    const int E = N_EDGES;
    const int* src = ei;
    const int* dst = ei + E;

    // resolve scratch symbol addresses
    float* h1;   cudaGetSymbolAddress((void**)&h1,   g_h1);
    float* agg1; cudaGetSymbolAddress((void**)&agg1, g_agg1);
    float* h2;   cudaGetSymbolAddress((void**)&h2,   g_h2);
    int*   deg;  cudaGetSymbolAddress((void**)&deg,  g_deg);

    // allow >48KB dynamic smem for the GEMMs
    cudaFuncSetAttribute(gemm_kernel<128>, cudaFuncAttributeMaxDynamicSharedMemorySize, 98304);
    cudaFuncSetAttribute(gemm_kernel<64>,  cudaFuncAttributeMaxDynamicSharedMemorySize, 65536);

    // --- zero deg, agg1, d_out ---
    zero_kernel<<<1024, 256>>>((float4*)deg, N / 4);                 // 100000/4 = 25000 ints*... (N%4==0)
    zero_kernel<<<2048, 256>>>((float4*)agg1, N * HID_C / 4);
    zero_kernel<<<2048, 256>>>((float4*)out, N * OUT_C / 4);

    // --- degree + dinv ---
    hist_kernel<<<(E + 255) / 256, 256>>>(dst, E);
    dinv_kernel<<<(N + 255) / 256, 256>>>(N);

    // --- layer 1 ---
    gemm_kernel<128><<<(N + 63) / 64, 256, 98304>>>(x, W1, h1, N);
    {
        size_t threads = (size_t)E * 32;
        int blocks = (int)((threads + 255) / 256);
        scatter_kernel<128><<<blocks, 256>>>(h1, src, dst, agg1, E);
    }
    combine_kernel<128, true><<<(N * (HID_C / 4) + 255) / 256, 256>>>(agg1, h1, b1, agg1, N);

    // --- layer 2 (h lives in agg1) ---
    gemm_kernel<64><<<(N + 63) / 64, 256, 65536>>>(agg1, W2, h2, N);
    {
        size_t threads = (size_t)E * 32;
        int blocks = (int)((threads + 255) / 256);
        scatter_kernel<64><<<blocks, 256>>>(h2, src, dst, out, E);
    }
    combine_kernel<64, false><<<(N * (OUT_C / 4) + 255) / 256, 256>>>(out, h2, b2, out, N);
}

// round 3
// speedup vs baseline: 1.7605x; 1.7605x over previous
#include <cuda_runtime.h>
#include <cuda_bf16.h>
#include <cstdint>

#define N_NODES 100000
#define N_EDGES 1600000
#define IN_C    128
#define HID_C   128
#define OUT_C   64

// ---------------- device scratch (no allocation allowed) ----------------
__device__ float g_hs1[(size_t)N_NODES * HID_C];   // (X@W1) * dinv[row]
__device__ float g_h [(size_t)N_NODES * HID_C];    // layer-1 output (post relu)
__device__ float g_hs2[(size_t)N_NODES * OUT_C];   // (h@W2) * dinv[row]
__device__ int   g_deg[N_NODES];
__device__ float g_dinv[N_NODES];
__device__ int   g_rowoff[N_NODES + 1];
__device__ int   g_cursor[N_NODES];
__device__ int   g_partial[512];
__device__ int   g_csrsrc[N_EDGES];

// ---------------- zero ints ----------------
__global__ void zero_int_kernel(int* __restrict__ p, int n) {
    int i = blockIdx.x * blockDim.x + threadIdx.x;
    int stride = gridDim.x * blockDim.x;
    for (; i < n; i += stride) p[i] = 0;
}

// ---------------- degree histogram ----------------
__global__ void hist_kernel(const int* __restrict__ dst, int E) {
    int i = blockIdx.x * blockDim.x + threadIdx.x;
    if (i < E) atomicAdd(&g_deg[dst[i]], 1);
}

__global__ void dinv_kernel(int n) {
    int i = blockIdx.x * blockDim.x + threadIdx.x;
    if (i < n) g_dinv[i] = rsqrtf((float)g_deg[i] + 1.0f);
}

// ---------------- 3-kernel exclusive scan of g_deg -> g_rowoff ----------------
// chunk = 256 elements per block
__global__ void scan1_kernel(int n) {
    __shared__ int sh[256];
    int t = threadIdx.x;
    int i = blockIdx.x * 256 + t;
    int v = (i < n) ? g_deg[i] : 0;
    sh[t] = v;
    __syncthreads();
    // tree reduce
    for (int s = 128; s > 0; s >>= 1) {
        if (t < s) sh[t] += sh[t + s];
        __syncthreads();
    }
    if (t == 0) g_partial[blockIdx.x] = sh[0];
}

__global__ void scan2_kernel(int nparts, int total_hint) {
    __shared__ int sh[512];
    int t = threadIdx.x;
    int v = (t < nparts) ? g_partial[t] : 0;
    sh[t] = v;
    __syncthreads();
    // Hillis-Steele inclusive scan
    for (int off = 1; off < 512; off <<= 1) {
        int add = (t >= off) ? sh[t - off] : 0;
        __syncthreads();
        sh[t] += add;
        __syncthreads();
    }
    if (t < nparts) g_partial[t] = sh[t] - v;  // exclusive
    if (t == 0) g_rowoff[N_NODES] = total_hint;
}

__global__ void scan3_kernel(int n) {
    __shared__ int sh[256];
    int t = threadIdx.x;
    int i = blockIdx.x * 256 + t;
    int v = (i < n) ? g_deg[i] : 0;
    sh[t] = v;
    __syncthreads();
    for (int off = 1; off < 256; off <<= 1) {
        int add = (t >= off) ? sh[t - off] : 0;
        __syncthreads();
        sh[t] += add;
        __syncthreads();
    }
    if (i < n) g_rowoff[i] = g_partial[blockIdx.x] + sh[t] - v;  // exclusive
}

// ---------------- bucket scatter: build csr src list ----------------
__global__ void bucket_kernel(const int* __restrict__ src, const int* __restrict__ dst, int E) {
    int e = blockIdx.x * blockDim.x + threadIdx.x;
    if (e >= E) return;
    int d = dst[e];
    int p = atomicAdd(&g_cursor[d], 1);
    g_csrsrc[g_rowoff[d] + p] = src[e];
}

// ---------------- fp32 SIMT GEMM: Y[n, NC] = (X[n,128] @ W[128,NC]) * dinv[row] ----------------
template <int NC>
__global__ void gemm_kernel(const float* __restrict__ X, const float* __restrict__ W,
                            float* __restrict__ Y, int nrows) {
    constexpr int K = 128;
    constexpr int BM = 64;
    constexpr int TCOLS = NC / 4;
    constexpr int TROWS = 256 / TCOLS;
    constexpr int MR = BM / TROWS;

    extern __shared__ float smem[];
    float* Ws = smem;            // K * NC
    float* Xs = smem + K * NC;   // BM * K

    int tid = threadIdx.x;

    for (int i = tid; i < K * NC / 4; i += 256)
        ((float4*)Ws)[i] = ((const float4*)W)[i];

    int row0 = blockIdx.x * BM;
    for (int i = tid; i < BM * K / 4; i += 256) {
        int r = i / (K / 4);
        int c = i % (K / 4);
        float4 v = make_float4(0.f, 0.f, 0.f, 0.f);
        if (row0 + r < nrows)
            v = ((const float4*)(X + (size_t)(row0 + r) * K))[c];
        ((float4*)Xs)[i] = v;
    }
    __syncthreads();

    int tc = tid % TCOLS;
    int tr = tid / TCOLS;

    float acc[MR][4];
#pragma unroll
    for (int i = 0; i < MR; i++)
#pragma unroll
        for (int j = 0; j < 4; j++) acc[i][j] = 0.f;

#pragma unroll 4
    for (int k = 0; k < K; k++) {
        float4 b = ((float4*)(Ws + k * NC))[tc];
#pragma unroll
        for (int i = 0; i < MR; i++) {
            float a = Xs[(tr * MR + i) * K + k];
            acc[i][0] += a * b.x;
            acc[i][1] += a * b.y;
            acc[i][2] += a * b.z;
            acc[i][3] += a * b.w;
        }
    }

#pragma unroll
    for (int i = 0; i < MR; i++) {
        int r = row0 + tr * MR + i;
        if (r < nrows) {
            float di = g_dinv[r];
            float4 v = make_float4(acc[i][0] * di, acc[i][1] * di,
                                   acc[i][2] * di, acc[i][3] * di);
            ((float4*)(Y + (size_t)r * NC))[tc] = v;
        }
    }
}

// ---------------- fused aggregate + combine ----------------
// out[node] = act( dinv[node] * (hs_self + sum_{s in N(node)} hs[s]) + bias )
// C = 128: one warp per node, each lane owns one float4 (32*16B = 512B row)
template <bool RELU>
__global__ void agg128_kernel(const float* __restrict__ HS, const float* __restrict__ bias,
                              float* __restrict__ out, int n) {
    int node = (int)((blockIdx.x * (size_t)blockDim.x + threadIdx.x) >> 5);
    int lane = threadIdx.x & 31;
    if (node >= n) return;
    int beg = g_rowoff[node];
    int cnt = g_deg[node];

    float4 acc = __ldg((const float4*)(HS + (size_t)node * 128) + lane);  // self term
    for (int j = 0; j < cnt; j++) {
        int s = __ldg(&g_csrsrc[beg + j]);
        float4 v = __ldg((const float4*)(HS + (size_t)s * 128) + lane);
        acc.x += v.x; acc.y += v.y; acc.z += v.z; acc.w += v.w;
    }
    float di = g_dinv[node];
    float4 bv = __ldg((const float4*)bias + lane);
    float4 r = make_float4(acc.x * di + bv.x, acc.y * di + bv.y,
                           acc.z * di + bv.z, acc.w * di + bv.w);
    if (RELU) {
        r.x = fmaxf(r.x, 0.f); r.y = fmaxf(r.y, 0.f);
        r.z = fmaxf(r.z, 0.f); r.w = fmaxf(r.w, 0.f);
    }
    ((float4*)(out + (size_t)node * 128))[lane] = r;
}

// C = 64: one warp per node, two half-warps process alternating edges
template <bool RELU>
__global__ void agg64_kernel(const float* __restrict__ HS, const float* __restrict__ bias,
                             float* __restrict__ out, int n) {
    int node = (int)((blockIdx.x * (size_t)blockDim.x + threadIdx.x) >> 5);
    int lane = threadIdx.x & 31;
    if (node >= n) return;
    int lane16 = lane & 15;
    int grp = lane >> 4;
    int beg = g_rowoff[node];
    int cnt = g_deg[node];

    float4 acc = make_float4(0.f, 0.f, 0.f, 0.f);
    if (grp == 0)
        acc = __ldg((const float4*)(HS + (size_t)node * 64) + lane16);  // self term
    for (int j = grp; j < cnt; j += 2) {
        int s = __ldg(&g_csrsrc[beg + j]);
        float4 v = __ldg((const float4*)(HS + (size_t)s * 64) + lane16);
        acc.x += v.x; acc.y += v.y; acc.z += v.z; acc.w += v.w;
    }
    // reduce the two half-warps
    acc.x += __shfl_xor_sync(0xFFFFFFFFu, acc.x, 16);
    acc.y += __shfl_xor_sync(0xFFFFFFFFu, acc.y, 16);
    acc.z += __shfl_xor_sync(0xFFFFFFFFu, acc.z, 16);
    acc.w += __shfl_xor_sync(0xFFFFFFFFu, acc.w, 16);

    if (grp == 0) {
        float di = g_dinv[node];
        float4 bv = __ldg((const float4*)bias + lane16);
        float4 r = make_float4(acc.x * di + bv.x, acc.y * di + bv.y,
                               acc.z * di + bv.z, acc.w * di + bv.w);
        if (RELU) {
            r.x = fmaxf(r.x, 0.f); r.y = fmaxf(r.y, 0.f);
            r.z = fmaxf(r.z, 0.f); r.w = fmaxf(r.w, 0.f);
        }
        ((float4*)(out + (size_t)node * 64))[lane16] = r;
    }
}

// ---------------- launch ----------------
extern "C" void kernel_launch(void* const* d_in, const int* in_sizes, int n_in,
                              void* d_out, int out_size) {
    const float* x  = (const float*)d_in[0];
    const int*   ei = (const int*)d_in[1];
    const float* W1 = (const float*)d_in[2];
    const float* b1 = (const float*)d_in[3];
    const float* W2 = (const float*)d_in[4];
    const float* b2 = (const float*)d_in[5];
    float* out = (float*)d_out;

    const int N = N_NODES;
    const int E = N_EDGES;
    const int* src = ei;
    const int* dst = ei + E;

    float* hs1; cudaGetSymbolAddress((void**)&hs1, g_hs1);
    float* h;   cudaGetSymbolAddress((void**)&h,   g_h);
    float* hs2; cudaGetSymbolAddress((void**)&hs2, g_hs2);
    int*   deg; cudaGetSymbolAddress((void**)&deg, g_deg);
    int*   cur; cudaGetSymbolAddress((void**)&cur, g_cursor);

    cudaFuncSetAttribute(gemm_kernel<128>, cudaFuncAttributeMaxDynamicSharedMemorySize, 98304);
    cudaFuncSetAttribute(gemm_kernel<64>,  cudaFuncAttributeMaxDynamicSharedMemorySize, 65536);

    const int NPARTS = (N + 255) / 256;  // 391

    // --- degree + dinv + CSR ---
    zero_int_kernel<<<256, 256>>>(deg, N);
    zero_int_kernel<<<256, 256>>>(cur, N);
    hist_kernel<<<(E + 255) / 256, 256>>>(dst, E);
    dinv_kernel<<<(N + 255) / 256, 256>>>(N);
    scan1_kernel<<<NPARTS, 256>>>(N);
    scan2_kernel<<<1, 512>>>(NPARTS, E);
    scan3_kernel<<<NPARTS, 256>>>(N);
    bucket_kernel<<<(E + 255) / 256, 256>>>(src, dst, E);

    // --- layer 1: hs1 = (x@W1)*dinv ; h = relu(dinv*(agg+self)+b1) ---
    gemm_kernel<128><<<(N + 63) / 64, 256, 98304>>>(x, W1, hs1, N);
    agg128_kernel<true><<<(N * 32 + 255) / 256, 256>>>(hs1, b1, h, N);

    // --- layer 2: hs2 = (h@W2)*dinv ; out = dinv*(agg+self)+b2 ---
    gemm_kernel<64><<<(N + 63) / 64, 256, 65536>>>(h, W2, hs2, N);
    agg64_kernel<false><<<(N * 32 + 255) / 256, 256>>>(hs2, b2, out, N);
}

// round 6
// speedup vs baseline: 1.9789x; 1.1241x over previous
#include <cuda_runtime.h>
#include <cuda_bf16.h>
#include <cstdint>

#define N_NODES 100000
#define N_EDGES 1600000
#define IN_C    128
#define HID_C   128
#define OUT_C   64

// ---------------- device scratch (no allocation allowed) ----------------
__device__ float g_hs1[(size_t)N_NODES * HID_C];   // (X@W1) * dinv[row]
__device__ float g_h [(size_t)N_NODES * HID_C];    // layer-1 output (post relu)
__device__ float g_hs2[(size_t)N_NODES * OUT_C];   // (h@W2) * dinv[row]
__device__ int   g_deg[N_NODES];
__device__ float g_dinv[N_NODES];
__device__ int   g_rowoff[N_NODES + 1];
__device__ int   g_cursor[N_NODES];
__device__ int   g_partial[512];
__device__ int   g_csrsrc[N_EDGES];

// ---------------- zero ints ----------------
__global__ void zero_int_kernel(int* __restrict__ p, int n) {
    int i = blockIdx.x * blockDim.x + threadIdx.x;
    int stride = gridDim.x * blockDim.x;
    for (; i < n; i += stride) p[i] = 0;
}

// ---------------- degree histogram ----------------
__global__ void hist_kernel(const int* __restrict__ dst, int E) {
    int i = blockIdx.x * blockDim.x + threadIdx.x;
    if (i < E) atomicAdd(&g_deg[dst[i]], 1);
}

__global__ void dinv_kernel(int n) {
    int i = blockIdx.x * blockDim.x + threadIdx.x;
    if (i < n) g_dinv[i] = rsqrtf((float)g_deg[i] + 1.0f);
}

// ---------------- 3-kernel exclusive scan of g_deg -> g_rowoff ----------------
__global__ void scan1_kernel(int n) {
    __shared__ int sh[256];
    int t = threadIdx.x;
    int i = blockIdx.x * 256 + t;
    int v = (i < n) ? g_deg[i] : 0;
    sh[t] = v;
    __syncthreads();
    for (int s = 128; s > 0; s >>= 1) {
        if (t < s) sh[t] += sh[t + s];
        __syncthreads();
    }
    if (t == 0) g_partial[blockIdx.x] = sh[0];
}

__global__ void scan2_kernel(int nparts, int total_hint) {
    __shared__ int sh[512];
    int t = threadIdx.x;
    int v = (t < nparts) ? g_partial[t] : 0;
    sh[t] = v;
    __syncthreads();
    for (int off = 1; off < 512; off <<= 1) {
        int add = (t >= off) ? sh[t - off] : 0;
        __syncthreads();
        sh[t] += add;
        __syncthreads();
    }
    if (t < nparts) g_partial[t] = sh[t] - v;
    if (t == 0) g_rowoff[N_NODES] = total_hint;
}

__global__ void scan3_kernel(int n) {
    __shared__ int sh[256];
    int t = threadIdx.x;
    int i = blockIdx.x * 256 + t;
    int v = (i < n) ? g_deg[i] : 0;
    sh[t] = v;
    __syncthreads();
    for (int off = 1; off < 256; off <<= 1) {
        int add = (t >= off) ? sh[t - off] : 0;
        __syncthreads();
        sh[t] += add;
        __syncthreads();
    }
    if (i < n) g_rowoff[i] = g_partial[blockIdx.x] + sh[t] - v;
}

// ---------------- bucket scatter: build csr src list ----------------
__global__ void bucket_kernel(const int* __restrict__ src, const int* __restrict__ dst, int E) {
    int e = blockIdx.x * blockDim.x + threadIdx.x;
    if (e >= E) return;
    int d = dst[e];
    int p = atomicAdd(&g_cursor[d], 1);
    g_csrsrc[g_rowoff[d] + p] = src[e];
}

// ---------------- tf32 cvt helper ----------------
__device__ __forceinline__ uint32_t f2tf32(float f) {
    uint32_t u;
    asm("cvt.rna.tf32.f32 %0, %1;" : "=r"(u) : "f"(f));
    return u;
}

// ---------------- mma.sync tf32 GEMM: Y[n, NC] = (X[n,128] @ W[128,NC]) * dinv[row] ----
// CTA: 256 thr / 8 warps. Tile M=128 (16 rows/warp), K=128, N=NC.
// A smem: [128][132] tf32 (bank = 4g+tg pattern, conflict-free fragment loads)
// B smem: [128][NC+4] tf32 = W as [k][n] (bank = 8tg+g pattern, conflict-free)
template <int NC>
__global__ void __launch_bounds__(256, 1)
mma_gemm_kernel(const float* __restrict__ X, const float* __restrict__ W,
                float* __restrict__ Y, int nrows) {
    constexpr int LA = 132;
    constexpr int LB = NC + 4;
    extern __shared__ uint32_t smu[];
    uint32_t* As = smu;                 // 128*LA
    uint32_t* Bs = smu + 128 * LA;      // 128*LB

    int tid = threadIdx.x;
    int row0 = blockIdx.x * 128;

    // ---- stage A (tf32-rounded), zero-fill tail rows ----
    for (int i = tid; i < 128 * 32; i += 256) {
        int r = i >> 5, c4 = i & 31;
        float4 v = make_float4(0.f, 0.f, 0.f, 0.f);
        if (row0 + r < nrows)
            v = ((const float4*)(X + (size_t)(row0 + r) * 128))[c4];
        uint4 u = make_uint4(f2tf32(v.x), f2tf32(v.y), f2tf32(v.z), f2tf32(v.w));
        *(uint4*)(As + r * LA + c4 * 4) = u;
    }
    // ---- stage B = W[k][n] (tf32-rounded) ----
    for (int i = tid; i < 128 * (NC / 4); i += 256) {
        int k = i / (NC / 4), n4 = i % (NC / 4);
        float4 v = ((const float4*)(W + (size_t)k * NC))[n4];
        uint4 u = make_uint4(f2tf32(v.x), f2tf32(v.y), f2tf32(v.z), f2tf32(v.w));
        *(uint4*)(Bs + k * LB + n4 * 4) = u;
    }
    __syncthreads();

    int wid = tid >> 5, lane = tid & 31;
    int g = lane >> 2, tg = lane & 3;
    int m0 = wid * 16;
    int rowA = row0 + m0 + g;
    int rowB = rowA + 8;
    float di0 = (rowA < nrows) ? g_dinv[rowA] : 0.f;
    float di1 = (rowB < nrows) ? g_dinv[rowB] : 0.f;

    // ---- preload all 16 k-step A fragments ----
    uint32_t a[16][4];
    const uint32_t* Ar0 = As + (m0 + g) * LA;
    const uint32_t* Ar1 = As + (m0 + g + 8) * LA;
#pragma unroll
    for (int k = 0; k < 16; k++) {
        a[k][0] = Ar0[k * 8 + tg];
        a[k][1] = Ar1[k * 8 + tg];
        a[k][2] = Ar0[k * 8 + tg + 4];
        a[k][3] = Ar1[k * 8 + tg + 4];
    }

    float* ya = Y + (size_t)rowA * NC + 2 * tg;
    float* yb = Y + (size_t)rowB * NC + 2 * tg;

#pragma unroll 2
    for (int nt = 0; nt < NC / 8; nt++) {
        int n0 = nt * 8;
        float c0 = 0.f, c1 = 0.f, c2 = 0.f, c3 = 0.f;
#pragma unroll
        for (int k = 0; k < 16; k++) {
            uint32_t b0 = Bs[(k * 8 + tg) * LB + n0 + g];
            uint32_t b1 = Bs[(k * 8 + tg + 4) * LB + n0 + g];
            asm volatile(
                "mma.sync.aligned.m16n8k8.row.col.f32.tf32.tf32.f32 "
                "{%0,%1,%2,%3}, {%4,%5,%6,%7}, {%8,%9}, {%0,%1,%2,%3};"
                : "+f"(c0), "+f"(c1), "+f"(c2), "+f"(c3)
                : "r"(a[k][0]), "r"(a[k][1]), "r"(a[k][2]), "r"(a[k][3]),
                  "r"(b0), "r"(b1));
        }
        if (rowA < nrows) *(float2*)(ya + n0) = make_float2(c0 * di0, c1 * di0);
        if (rowB < nrows) *(float2*)(yb + n0) = make_float2(c2 * di1, c3 * di1);
    }
}

// ---------------- fused aggregate + combine ----------------
template <bool RELU>
__global__ void agg128_kernel(const float* __restrict__ HS, const float* __restrict__ bias,
                              float* __restrict__ out, int n) {
    int node = (int)((blockIdx.x * (size_t)blockDim.x + threadIdx.x) >> 5);
    int lane = threadIdx.x & 31;
    if (node >= n) return;
    int beg = g_rowoff[node];
    int cnt = g_deg[node];

    float4 acc = __ldg((const float4*)(HS + (size_t)node * 128) + lane);
    for (int j = 0; j < cnt; j++) {
        int s = __ldg(&g_csrsrc[beg + j]);
        float4 v = __ldg((const float4*)(HS + (size_t)s * 128) + lane);
        acc.x += v.x; acc.y += v.y; acc.z += v.z; acc.w += v.w;
    }
    float di = g_dinv[node];
    float4 bv = __ldg((const float4*)bias + lane);
    float4 r = make_float4(acc.x * di + bv.x, acc.y * di + bv.y,
                           acc.z * di + bv.z, acc.w * di + bv.w);
    if (RELU) {
        r.x = fmaxf(r.x, 0.f); r.y = fmaxf(r.y, 0.f);
        r.z = fmaxf(r.z, 0.f); r.w = fmaxf(r.w, 0.f);
    }
    ((float4*)(out + (size_t)node * 128))[lane] = r;
}

template <bool RELU>
__global__ void agg64_kernel(const float* __restrict__ HS, const float* __restrict__ bias,
                             float* __restrict__ out, int n) {
    int node = (int)((blockIdx.x * (size_t)blockDim.x + threadIdx.x) >> 5);
    int lane = threadIdx.x & 31;
    if (node >= n) return;
    int lane16 = lane & 15;
    int grp = lane >> 4;
    int beg = g_rowoff[node];
    int cnt = g_deg[node];

    float4 acc = make_float4(0.f, 0.f, 0.f, 0.f);
    if (grp == 0)
        acc = __ldg((const float4*)(HS + (size_t)node * 64) + lane16);
    for (int j = grp; j < cnt; j += 2) {
        int s = __ldg(&g_csrsrc[beg + j]);
        float4 v = __ldg((const float4*)(HS + (size_t)s * 64) + lane16);
        acc.x += v.x; acc.y += v.y; acc.z += v.z; acc.w += v.w;
    }
    acc.x += __shfl_xor_sync(0xFFFFFFFFu, acc.x, 16);
    acc.y += __shfl_xor_sync(0xFFFFFFFFu, acc.y, 16);
    acc.z += __shfl_xor_sync(0xFFFFFFFFu, acc.z, 16);
    acc.w += __shfl_xor_sync(0xFFFFFFFFu, acc.w, 16);

    if (grp == 0) {
        float di = g_dinv[node];
        float4 bv = __ldg((const float4*)bias + lane16);
        float4 r = make_float4(acc.x * di + bv.x, acc.y * di + bv.y,
                               acc.z * di + bv.z, acc.w * di + bv.w);
        if (RELU) {
            r.x = fmaxf(r.x, 0.f); r.y = fmaxf(r.y, 0.f);
            r.z = fmaxf(r.z, 0.f); r.w = fmaxf(r.w, 0.f);
        }
        ((float4*)(out + (size_t)node * 64))[lane16] = r;
    }
}

// ---------------- launch ----------------
extern "C" void kernel_launch(void* const* d_in, const int* in_sizes, int n_in,
                              void* d_out, int out_size) {
    const float* x  = (const float*)d_in[0];
    const int*   ei = (const int*)d_in[1];
    const float* W1 = (const float*)d_in[2];
    const float* b1 = (const float*)d_in[3];
    const float* W2 = (const float*)d_in[4];
    const float* b2 = (const float*)d_in[5];
    float* out = (float*)d_out;

    const int N = N_NODES;
    const int E = N_EDGES;
    const int* src = ei;
    const int* dst = ei + E;

    float* hs1; cudaGetSymbolAddress((void**)&hs1, g_hs1);
    float* h;   cudaGetSymbolAddress((void**)&h,   g_h);
    float* hs2; cudaGetSymbolAddress((void**)&hs2, g_hs2);
    int*   deg; cudaGetSymbolAddress((void**)&deg, g_deg);
    int*   cur; cudaGetSymbolAddress((void**)&cur, g_cursor);

    // dynamic smem: A[128][132] + B[128][NC+4] in uint32
    const int SMEM1 = (128 * 132 + 128 * 132) * 4;  // 135168
    const int SMEM2 = (128 * 132 + 128 * 68) * 4;   // 102400
    cudaFuncSetAttribute(mma_gemm_kernel<128>, cudaFuncAttributeMaxDynamicSharedMemorySize, SMEM1);
    cudaFuncSetAttribute(mma_gemm_kernel<64>,  cudaFuncAttributeMaxDynamicSharedMemorySize, SMEM2);

    const int NPARTS = (N + 255) / 256;  // 391

    // --- degree + dinv + CSR ---
    zero_int_kernel<<<256, 256>>>(deg, N);
    zero_int_kernel<<<256, 256>>>(cur, N);
    hist_kernel<<<(E + 255) / 256, 256>>>(dst, E);
    dinv_kernel<<<(N + 255) / 256, 256>>>(N);
    scan1_kernel<<<NPARTS, 256>>>(N);
    scan2_kernel<<<1, 512>>>(NPARTS, E);
    scan3_kernel<<<NPARTS, 256>>>(N);
    bucket_kernel<<<(E + 255) / 256, 256>>>(src, dst, E);

    const int MBLKS = (N + 127) / 128;  // 782

    // --- layer 1: hs1 = (x@W1)*dinv ; h = relu(dinv*(agg+self)+b1) ---
    mma_gemm_kernel<128><<<MBLKS, 256, SMEM1>>>(x, W1, hs1, N);
    agg128_kernel<true><<<(N * 32 + 255) / 256, 256>>>(hs1, b1, h, N);

    // --- layer 2: hs2 = (h@W2)*dinv ; out = dinv*(agg+self)+b2 ---
    mma_gemm_kernel<64><<<MBLKS, 256, SMEM2>>>(h, W2, hs2, N);
    agg64_kernel<false><<<(N * 32 + 255) / 256, 256>>>(hs2, b2, out, N);
}